// round 7
// baseline (speedup 1.0000x reference)
#include <cuda_runtime.h>

#define NV 4096            // nodes per graph
#define NB 32              // batch size (== warp size, load-bearing)
#define BN (NV * NB)       // 131072
#define CAP 256            // ELL row capacity (mean degree 128, +11 sigma headroom)
#define CSTRIDE 32         // counter padding: 1 counter per 128B line

// ---- scratch (device globals; counters zero at entry: BSS on first call,
//      self-zeroed by k_mu/k_dx on every call) ----
__device__ float  g_xt  [BN];            // x,  node-major [node][batch]
__device__ float  g_fxt [BN];            // tanh(x), node-major
__device__ float  g_epst[BN];            // eps = x - mu, node-major
__device__ int    g_cnt_dst[NV * CSTRIDE];   // padded: index node*32
__device__ int    g_cnt_src[NV * CSTRIDE];
__device__ float2 g_ellF[NV * CAP];      // rows keyed by dst: (src*32, w)
__device__ float2 g_ellB[NV * CAP];      // rows keyed by src: (dst*32, w)

// One edge insert into both ELL structures.
__device__ __forceinline__ void ell_insert(int s, int d, float wt) {
    int p = atomicAdd(&g_cnt_dst[d << 5], 1);
    if (p < CAP) g_ellF[(d << 8) + p] = make_float2(__int_as_float(s << 5), wt);
    int q = atomicAdd(&g_cnt_src[s << 5], 1);
    if (q < CAP) g_ellB[(s << 8) + q] = make_float2(__int_as_float(d << 5), wt);
}

// ============================================================================
// Fused prep (transpose + tanh) + ELL build. 256 threads/block.
// blocks [0,128)   : transpose x [B,N] -> node-major, tanh
// blocks [128,384) : build, 8 edges/thread (16 ATOMG chains in flight)
// ============================================================================
__global__ void k_pb(const float* __restrict__ x,
                     const float* __restrict__ w,
                     const int*   __restrict__ esrc,
                     const int*   __restrict__ edst, int E) {
    if (blockIdx.x < 128) {
        __shared__ float s[32][33];
        int tx  = threadIdx.x & 31;
        int ty0 = threadIdx.x >> 5;          // 0..7
        int i0  = blockIdx.x * 32;
        #pragma unroll
        for (int r = 0; r < 4; r++) {
            int ty = ty0 + (r << 3);
            s[ty][tx] = x[ty * NV + i0 + tx];            // batch-major read
        }
        __syncthreads();
        #pragma unroll
        for (int r = 0; r < 4; r++) {
            int ty = ty0 + (r << 3);
            float xv = s[tx][ty];
            int o = (i0 + ty) * NB + tx;                 // node-major write
            g_xt[o]  = xv;
            g_fxt[o] = tanhf(xv);
        }
        return;
    }
    // ---- build: 8 edges per thread ----
    int t  = (blockIdx.x - 128) * 256 + threadIdx.x;
    int e0 = t << 3;
    if (e0 >= E) return;
    if (e0 + 8 <= E) {
        int4   sa = *(const int4*)  (esrc + e0);
        int4   sb = *(const int4*)  (esrc + e0 + 4);
        int4   da = *(const int4*)  (edst + e0);
        int4   db = *(const int4*)  (edst + e0 + 4);
        float4 wa = *(const float4*)(w    + e0);
        float4 wb = *(const float4*)(w    + e0 + 4);
        int p0 = atomicAdd(&g_cnt_dst[da.x << 5], 1);
        int p1 = atomicAdd(&g_cnt_dst[da.y << 5], 1);
        int p2 = atomicAdd(&g_cnt_dst[da.z << 5], 1);
        int p3 = atomicAdd(&g_cnt_dst[da.w << 5], 1);
        int p4 = atomicAdd(&g_cnt_dst[db.x << 5], 1);
        int p5 = atomicAdd(&g_cnt_dst[db.y << 5], 1);
        int p6 = atomicAdd(&g_cnt_dst[db.z << 5], 1);
        int p7 = atomicAdd(&g_cnt_dst[db.w << 5], 1);
        int q0 = atomicAdd(&g_cnt_src[sa.x << 5], 1);
        int q1 = atomicAdd(&g_cnt_src[sa.y << 5], 1);
        int q2 = atomicAdd(&g_cnt_src[sa.z << 5], 1);
        int q3 = atomicAdd(&g_cnt_src[sa.w << 5], 1);
        int q4 = atomicAdd(&g_cnt_src[sb.x << 5], 1);
        int q5 = atomicAdd(&g_cnt_src[sb.y << 5], 1);
        int q6 = atomicAdd(&g_cnt_src[sb.z << 5], 1);
        int q7 = atomicAdd(&g_cnt_src[sb.w << 5], 1);
        if (p0 < CAP) g_ellF[(da.x << 8) + p0] = make_float2(__int_as_float(sa.x << 5), wa.x);
        if (p1 < CAP) g_ellF[(da.y << 8) + p1] = make_float2(__int_as_float(sa.y << 5), wa.y);
        if (p2 < CAP) g_ellF[(da.z << 8) + p2] = make_float2(__int_as_float(sa.z << 5), wa.z);
        if (p3 < CAP) g_ellF[(da.w << 8) + p3] = make_float2(__int_as_float(sa.w << 5), wa.w);
        if (p4 < CAP) g_ellF[(db.x << 8) + p4] = make_float2(__int_as_float(sb.x << 5), wb.x);
        if (p5 < CAP) g_ellF[(db.y << 8) + p5] = make_float2(__int_as_float(sb.y << 5), wb.y);
        if (p6 < CAP) g_ellF[(db.z << 8) + p6] = make_float2(__int_as_float(sb.z << 5), wb.z);
        if (p7 < CAP) g_ellF[(db.w << 8) + p7] = make_float2(__int_as_float(sb.w << 5), wb.w);
        if (q0 < CAP) g_ellB[(sa.x << 8) + q0] = make_float2(__int_as_float(da.x << 5), wa.x);
        if (q1 < CAP) g_ellB[(sa.y << 8) + q1] = make_float2(__int_as_float(da.y << 5), wa.y);
        if (q2 < CAP) g_ellB[(sa.z << 8) + q2] = make_float2(__int_as_float(da.z << 5), wa.z);
        if (q3 < CAP) g_ellB[(sa.w << 8) + q3] = make_float2(__int_as_float(da.w << 5), wa.w);
        if (q4 < CAP) g_ellB[(sb.x << 8) + q4] = make_float2(__int_as_float(db.x << 5), wb.x);
        if (q5 < CAP) g_ellB[(sb.y << 8) + q5] = make_float2(__int_as_float(db.y << 5), wb.y);
        if (q6 < CAP) g_ellB[(sb.z << 8) + q6] = make_float2(__int_as_float(db.z << 5), wb.z);
        if (q7 < CAP) g_ellB[(sb.w << 8) + q7] = make_float2(__int_as_float(db.w << 5), wb.w);
    } else {
        for (int e = e0; e < E; e++) ell_insert(esrc[e], edst[e], w[e]);
    }
}

// SpMM over smem-staged row, pair range [pb,pe): one LDS.128 = 2 edges'
// (colOff, w), scalar 1-line gathers via pre-offset lane pointer tabl.
// Warp q==3 handles the odd trailing edge.
__device__ __forceinline__ float spmm_smem(const float2* row,
                                           const float* __restrict__ tabl,
                                           int pb, int pe, int n, int q) {
    const float4* rv = (const float4*)row;      // smem, 16B-aligned
    float a0 = 0.f, a1 = 0.f, a2 = 0.f, a3 = 0.f;
    int p = pb;
    for (; p + 4 <= pe; p += 4) {
        float4 f0 = rv[p + 0];                  // edges 2p, 2p+1
        float4 f1 = rv[p + 1];
        float4 f2 = rv[p + 2];
        float4 f3 = rv[p + 3];
        float v0 = tabl[__float_as_int(f0.x)];
        float v1 = tabl[__float_as_int(f0.z)];
        float v2 = tabl[__float_as_int(f1.x)];
        float v3 = tabl[__float_as_int(f1.z)];
        float v4 = tabl[__float_as_int(f2.x)];
        float v5 = tabl[__float_as_int(f2.z)];
        float v6 = tabl[__float_as_int(f3.x)];
        float v7 = tabl[__float_as_int(f3.z)];
        a0 = fmaf(f0.y, v0, a0); a1 = fmaf(f0.w, v1, a1);
        a2 = fmaf(f1.y, v2, a2); a3 = fmaf(f1.w, v3, a3);
        a0 = fmaf(f2.y, v4, a0); a1 = fmaf(f2.w, v5, a1);
        a2 = fmaf(f3.y, v6, a2); a3 = fmaf(f3.w, v7, a3);
    }
    for (; p < pe; p++) {
        float4 f0 = rv[p];
        a0 = fmaf(f0.y, tabl[__float_as_int(f0.x)], a0);
        a1 = fmaf(f0.w, tabl[__float_as_int(f0.z)], a1);
    }
    if (q == 3 && (n & 1)) {
        float2 e0 = row[n - 1];
        a0 = fmaf(e0.y, tabl[__float_as_int(e0.x)], a0);
    }
    return (a0 + a1) + (a2 + a3);
}

// Forward SpMM: mu = sum w * fx[src]; eps = x - mu (node-major);
// mu written straight to out[0] batch-major (scattered 4B stores).
__global__ void __launch_bounds__(256, 8) k_mu(float* __restrict__ out) {
    __shared__ float2 srow[2][CAP];
    __shared__ float  part[2][4][32];
    int warp  = threadIdx.x >> 5;
    int lane  = threadIdx.x & 31;
    int local = warp >> 2;
    int q     = warp & 3;
    int node0 = blockIdx.x << 1;

    int n0 = min(g_cnt_dst[node0 << 5],       CAP);
    int n1 = min(g_cnt_dst[(node0 + 1) << 5], CAP);
    for (int i = threadIdx.x; i < n0; i += 256) srow[0][i] = g_ellF[(node0 << 8) + i];
    for (int i = threadIdx.x; i < n1; i += 256) srow[1][i] = g_ellF[((node0 + 1) << 8) + i];
    __syncthreads();

    int n     = local ? n1 : n0;
    int npair = n >> 1;
    int pb    = (npair * q) >> 2;
    int pe    = (npair * (q + 1)) >> 2;
    const float* tabl = g_fxt + lane;

    part[local][q][lane] = spmm_smem(srow[local], tabl, pb, pe, n, q);
    __syncthreads();

    if (q == 0) {
        float mu = (part[local][0][lane] + part[local][1][lane])
                 + (part[local][2][lane] + part[local][3][lane]);
        int node = node0 + local;
        int o = (node << 5) + lane;
        g_epst[o] = g_xt[o] - mu;
        out[lane * NV + node] = mu;                     // batch-major, scattered
        if (lane == 0) g_cnt_dst[node << 5] = 0;        // restore invariant
    }
}

// Backward SpMM: dx = -eps + (1-fx^2) * sum w * eps[dst];
// dx written straight to out[1] batch-major.
__global__ void __launch_bounds__(256, 8) k_dx(float* __restrict__ out) {
    __shared__ float2 srow[2][CAP];
    __shared__ float  part[2][4][32];
    int warp  = threadIdx.x >> 5;
    int lane  = threadIdx.x & 31;
    int local = warp >> 2;
    int q     = warp & 3;
    int node0 = blockIdx.x << 1;

    int n0 = min(g_cnt_src[node0 << 5],       CAP);
    int n1 = min(g_cnt_src[(node0 + 1) << 5], CAP);
    for (int i = threadIdx.x; i < n0; i += 256) srow[0][i] = g_ellB[(node0 << 8) + i];
    for (int i = threadIdx.x; i < n1; i += 256) srow[1][i] = g_ellB[((node0 + 1) << 8) + i];
    __syncthreads();

    int n     = local ? n1 : n0;
    int npair = n >> 1;
    int pb    = (npair * q) >> 2;
    int pe    = (npair * (q + 1)) >> 2;
    const float* tabl = g_epst + lane;

    part[local][q][lane] = spmm_smem(srow[local], tabl, pb, pe, n, q);
    __syncthreads();

    if (q == 0) {
        float acc = (part[local][0][lane] + part[local][1][lane])
                  + (part[local][2][lane] + part[local][3][lane]);
        int node = node0 + local;
        int o = (node << 5) + lane;
        float eps = g_epst[o];
        float fx  = g_fxt[o];
        out[BN + lane * NV + node] = fmaf(fmaf(-fx, fx, 1.0f), acc, -eps);
        if (lane == 0) g_cnt_src[node << 5] = 0;        // restore invariant
    }
}

extern "C" void kernel_launch(void* const* d_in, const int* in_sizes, int n_in,
                              void* d_out, int out_size) {
    const float* x    = (const float*)d_in[0];
    const float* w    = (const float*)d_in[1];
    const int*   esrc = (const int*)d_in[2];
    const int*   edst = (const int*)d_in[3];
    float*       out  = (float*)d_out;
    int E = in_sizes[1];

    k_pb <<<128 + ((E + 7) / 8 + 255) / 256, 256>>>(x, w, esrc, edst, E);
    k_mu <<<NV / 2, 256>>>(out);
    k_dx <<<NV / 2, 256>>>(out);
}

// round 8
// speedup vs baseline: 1.1031x; 1.1031x over previous
#include <cuda_runtime.h>

#define NV 4096            // nodes per graph
#define NB 32              // batch size (== warp size, load-bearing)
#define BN (NV * NB)       // 131072
#define CAP 256            // ELL row capacity (mean degree 128, +11 sigma headroom)
#define CSTRIDE 32         // counter padding: 1 counter per 128B line

// ---- scratch (device globals; counters zero at entry: BSS on first call,
//      self-zeroed by k_mu/k_dx on every call) ----
__device__ float  g_xt  [BN];            // x,  node-major [node][batch]
__device__ float  g_fxt [BN];            // tanh(x), node-major
__device__ float  g_epst[BN];            // eps = x - mu, node-major
__device__ int    g_cnt_dst[NV * CSTRIDE];   // padded: index node*32
__device__ int    g_cnt_src[NV * CSTRIDE];
__device__ float2 g_ellF[NV * CAP];      // rows keyed by dst: (src*32, w)
__device__ float2 g_ellB[NV * CAP];      // rows keyed by src: (dst*32, w)

// Transpose x [B,N] -> node-major, apply tanh. CTA = 1024 = 32x32 tile.
__global__ void k_prep(const float* __restrict__ x) {
    __shared__ float s[32][33];
    int tx = threadIdx.x & 31;
    int ty = threadIdx.x >> 5;
    int i0 = blockIdx.x * 32;

    s[ty][tx] = x[ty * NV + i0 + tx];          // batch-major read (coalesced)
    __syncthreads();

    float xv = s[tx][ty];
    int o = (i0 + ty) * NB + tx;               // node-major write (coalesced)
    g_xt[o]  = xv;
    g_fxt[o] = tanhf(xv);
}

// Build both ELL structures; 4 edges/thread (R6-proven: 512 CTAs, good occ).
// Counters padded to 128B stride; column offsets stored pre-scaled (*32).
__global__ void k_build(const float* __restrict__ w,
                        const int*   __restrict__ esrc,
                        const int*   __restrict__ edst, int E) {
    int t  = blockIdx.x * blockDim.x + threadIdx.x;
    int e0 = t << 2;
    if (e0 >= E) return;
    if (e0 + 4 <= E) {
        int4   s4 = *(const int4*)  (esrc + e0);
        int4   d4 = *(const int4*)  (edst + e0);
        float4 w4 = *(const float4*)(w    + e0);
        int p0 = atomicAdd(&g_cnt_dst[d4.x << 5], 1);
        int p1 = atomicAdd(&g_cnt_dst[d4.y << 5], 1);
        int p2 = atomicAdd(&g_cnt_dst[d4.z << 5], 1);
        int p3 = atomicAdd(&g_cnt_dst[d4.w << 5], 1);
        int q0 = atomicAdd(&g_cnt_src[s4.x << 5], 1);
        int q1 = atomicAdd(&g_cnt_src[s4.y << 5], 1);
        int q2 = atomicAdd(&g_cnt_src[s4.z << 5], 1);
        int q3 = atomicAdd(&g_cnt_src[s4.w << 5], 1);
        if (p0 < CAP) g_ellF[(d4.x << 8) + p0] = make_float2(__int_as_float(s4.x << 5), w4.x);
        if (p1 < CAP) g_ellF[(d4.y << 8) + p1] = make_float2(__int_as_float(s4.y << 5), w4.y);
        if (p2 < CAP) g_ellF[(d4.z << 8) + p2] = make_float2(__int_as_float(s4.z << 5), w4.z);
        if (p3 < CAP) g_ellF[(d4.w << 8) + p3] = make_float2(__int_as_float(s4.w << 5), w4.w);
        if (q0 < CAP) g_ellB[(s4.x << 8) + q0] = make_float2(__int_as_float(d4.x << 5), w4.x);
        if (q1 < CAP) g_ellB[(s4.y << 8) + q1] = make_float2(__int_as_float(d4.y << 5), w4.y);
        if (q2 < CAP) g_ellB[(s4.z << 8) + q2] = make_float2(__int_as_float(d4.z << 5), w4.z);
        if (q3 < CAP) g_ellB[(s4.w << 8) + q3] = make_float2(__int_as_float(d4.w << 5), w4.w);
    } else {
        for (int e = e0; e < E; e++) {
            int s = esrc[e], d = edst[e];
            float wt = w[e];
            int p = atomicAdd(&g_cnt_dst[d << 5], 1);
            if (p < CAP) g_ellF[(d << 8) + p] = make_float2(__int_as_float(s << 5), wt);
            int q = atomicAdd(&g_cnt_src[s << 5], 1);
            if (q < CAP) g_ellB[(s << 8) + q] = make_float2(__int_as_float(d << 5), wt);
        }
    }
}

// SpMM over smem-staged row, pair range [pb,pe): one LDS.128 = 2 edges'
// (colOff, w), scalar 1-line gathers via pre-offset lane pointer tabl.
// Warp q==3 handles the odd trailing edge.
__device__ __forceinline__ float spmm_smem(const float2* row,
                                           const float* __restrict__ tabl,
                                           int pb, int pe, int n, int q) {
    const float4* rv = (const float4*)row;      // smem, 16B-aligned
    float a0 = 0.f, a1 = 0.f, a2 = 0.f, a3 = 0.f;
    int p = pb;
    for (; p + 4 <= pe; p += 4) {
        float4 f0 = rv[p + 0];                  // edges 2p, 2p+1
        float4 f1 = rv[p + 1];
        float4 f2 = rv[p + 2];
        float4 f3 = rv[p + 3];
        float v0 = tabl[__float_as_int(f0.x)];
        float v1 = tabl[__float_as_int(f0.z)];
        float v2 = tabl[__float_as_int(f1.x)];
        float v3 = tabl[__float_as_int(f1.z)];
        float v4 = tabl[__float_as_int(f2.x)];
        float v5 = tabl[__float_as_int(f2.z)];
        float v6 = tabl[__float_as_int(f3.x)];
        float v7 = tabl[__float_as_int(f3.z)];
        a0 = fmaf(f0.y, v0, a0); a1 = fmaf(f0.w, v1, a1);
        a2 = fmaf(f1.y, v2, a2); a3 = fmaf(f1.w, v3, a3);
        a0 = fmaf(f2.y, v4, a0); a1 = fmaf(f2.w, v5, a1);
        a2 = fmaf(f3.y, v6, a2); a3 = fmaf(f3.w, v7, a3);
    }
    for (; p < pe; p++) {
        float4 f0 = rv[p];
        a0 = fmaf(f0.y, tabl[__float_as_int(f0.x)], a0);
        a1 = fmaf(f0.w, tabl[__float_as_int(f0.z)], a1);
    }
    if (q == 3 && (n & 1)) {
        float2 e0 = row[n - 1];
        a0 = fmaf(e0.y, tabl[__float_as_int(e0.x)], a0);
    }
    return (a0 + a1) + (a2 + a3);
}

// Forward SpMM: mu = sum w * fx[src]; eps = x - mu (node-major);
// mu written straight to out[0] batch-major (scattered 4B stores).
__global__ void __launch_bounds__(256, 8) k_mu(float* __restrict__ out) {
    __shared__ float2 srow[2][CAP];
    __shared__ float  part[2][4][32];
    int warp  = threadIdx.x >> 5;
    int lane  = threadIdx.x & 31;
    int local = warp >> 2;
    int q     = warp & 3;
    int node0 = blockIdx.x << 1;

    int n0 = min(g_cnt_dst[node0 << 5],       CAP);
    int n1 = min(g_cnt_dst[(node0 + 1) << 5], CAP);
    for (int i = threadIdx.x; i < n0; i += 256) srow[0][i] = g_ellF[(node0 << 8) + i];
    for (int i = threadIdx.x; i < n1; i += 256) srow[1][i] = g_ellF[((node0 + 1) << 8) + i];
    __syncthreads();

    int n     = local ? n1 : n0;
    int npair = n >> 1;
    int pb    = (npair * q) >> 2;
    int pe    = (npair * (q + 1)) >> 2;
    const float* tabl = g_fxt + lane;

    part[local][q][lane] = spmm_smem(srow[local], tabl, pb, pe, n, q);
    __syncthreads();

    if (q == 0) {
        float mu = (part[local][0][lane] + part[local][1][lane])
                 + (part[local][2][lane] + part[local][3][lane]);
        int node = node0 + local;
        int o = (node << 5) + lane;
        g_epst[o] = g_xt[o] - mu;
        out[lane * NV + node] = mu;                     // batch-major, scattered
        if (lane == 0) g_cnt_dst[node << 5] = 0;        // restore invariant
    }
}

// Backward SpMM: dx = -eps + (1-fx^2) * sum w * eps[dst];
// dx written straight to out[1] batch-major.
__global__ void __launch_bounds__(256, 8) k_dx(float* __restrict__ out) {
    __shared__ float2 srow[2][CAP];
    __shared__ float  part[2][4][32];
    int warp  = threadIdx.x >> 5;
    int lane  = threadIdx.x & 31;
    int local = warp >> 2;
    int q     = warp & 3;
    int node0 = blockIdx.x << 1;

    int n0 = min(g_cnt_src[node0 << 5],       CAP);
    int n1 = min(g_cnt_src[(node0 + 1) << 5], CAP);
    for (int i = threadIdx.x; i < n0; i += 256) srow[0][i] = g_ellB[(node0 << 8) + i];
    for (int i = threadIdx.x; i < n1; i += 256) srow[1][i] = g_ellB[((node0 + 1) << 8) + i];
    __syncthreads();

    int n     = local ? n1 : n0;
    int npair = n >> 1;
    int pb    = (npair * q) >> 2;
    int pe    = (npair * (q + 1)) >> 2;
    const float* tabl = g_epst + lane;

    part[local][q][lane] = spmm_smem(srow[local], tabl, pb, pe, n, q);
    __syncthreads();

    if (q == 0) {
        float acc = (part[local][0][lane] + part[local][1][lane])
                  + (part[local][2][lane] + part[local][3][lane]);
        int node = node0 + local;
        int o = (node << 5) + lane;
        float eps = g_epst[o];
        float fx  = g_fxt[o];
        out[BN + lane * NV + node] = fmaf(fmaf(-fx, fx, 1.0f), acc, -eps);
        if (lane == 0) g_cnt_src[node << 5] = 0;        // restore invariant
    }
}

extern "C" void kernel_launch(void* const* d_in, const int* in_sizes, int n_in,
                              void* d_out, int out_size) {
    const float* x    = (const float*)d_in[0];
    const float* w    = (const float*)d_in[1];
    const int*   esrc = (const int*)d_in[2];
    const int*   edst = (const int*)d_in[3];
    float*       out  = (float*)d_out;
    int E = in_sizes[1];

    k_prep <<<NV / 32, 1024>>>(x);
    k_build<<<((E + 3) / 4 + 255) / 256, 256>>>(w, esrc, edst, E);
    k_mu   <<<NV / 2, 256>>>(out);
    k_dx   <<<NV / 2, 256>>>(out);
}